// round 4
// baseline (speedup 1.0000x reference)
#include <cuda_runtime.h>
#include <math.h>

// Problem constants (fixed by the dataset instance)
#define Bsz   16384
#define Csz   2048
#define Ksz   200
#define NCsz  1000
#define SLOTS 32

// GEMM1 tiling
#define BM      64
#define BK      32
#define NP      224   // K (concept) dim padded 200 -> 224 = 32*7
#define S2      36    // padded k-stride in smem
#define THREADS 256

// GEMM2 tiling
#define TNO 128
#define RB  128

// ---------------- device scratch (no allocations allowed) ----------------
__device__ float g_proto[Ksz * Csz];         // normalized prototypes = c / max(||c||,1e-12)
__device__ float g_fcwT[Ksz * NCsz];         // fc_w transposed: [K][NC]
__device__ int   g_sidx[Bsz * SLOTS];        // per-row surviving indices (padded)
__device__ float g_sval[Bsz * SLOTS];        // per-row surviving LN'd values (padded)

// ---------------- normalize prototypes exactly like the reference ----------------
__global__ void k_norm_kernel(const float* __restrict__ concepts) {
    __shared__ float red[THREADS];
    __shared__ float nrm;
    int k = blockIdx.x;
    const float* row = concepts + (size_t)k * Csz;
    float s = 0.f;
    for (int c = threadIdx.x; c < Csz; c += THREADS) {
        float v = row[c];
        s = fmaf(v, v, s);
    }
    red[threadIdx.x] = s;
    __syncthreads();
    for (int off = THREADS / 2; off > 0; off >>= 1) {
        if (threadIdx.x < off) red[threadIdx.x] += red[threadIdx.x + off];
        __syncthreads();
    }
    if (threadIdx.x == 0) nrm = fmaxf(sqrtf(red[0]), 1e-12f);
    __syncthreads();
    float n = nrm;
    for (int c = threadIdx.x; c < Csz; c += THREADS)
        g_proto[(size_t)k * Csz + c] = row[c] / n;   // div.rn, matches F.normalize rounding
}

// ---------------- tiled transpose fc_w [NC,K] -> [K,NC] ----------------
__global__ void k_tr_kernel(const float* __restrict__ fc_w) {
    __shared__ float tile[32][33];
    const int n0 = blockIdx.x * 32;
    const int k0 = blockIdx.y * 32;
    const int tx = threadIdx.x;       // 0..31
    const int ty = threadIdx.y;       // 0..7
    #pragma unroll
    for (int i = 0; i < 32; i += 8) {
        int n = n0 + ty + i, k = k0 + tx;
        tile[ty + i][tx] = (n < NCsz && k < Ksz) ? fc_w[(size_t)n * Ksz + k] : 0.f;
    }
    __syncthreads();
    #pragma unroll
    for (int i = 0; i < 32; i += 8) {
        int k = k0 + ty + i, n = n0 + tx;
        if (k < Ksz && n < NCsz)
            g_fcwT[(size_t)k * NCsz + n] = tile[tx][ty + i];
    }
}

// ---------------- fused GEMM1 + LayerNorm + top-k select ----------------
// FMA sequence is IDENTICAL to the passing round-3 kernel (same kk,i,j order,
// same per-BK chunked accumulation); only the smem operand loads are widened
// to float2 to halve LDS instruction issue.
__global__ __launch_bounds__(THREADS, 2)
void k_main_kernel(const float* __restrict__ x,
                   const float* __restrict__ lnw,
                   const float* __restrict__ lnb,
                   const int*   __restrict__ dfi) {
    __shared__ float smem[(BM + NP) * S2];   // 10368 floats (reused as feat[32][200])
    float* sx = smem;                  // [BM][S2]
    float* sp = smem + BM * S2;        // [NP][S2]

    const int tid = threadIdx.x;
    const int tm  = tid & 7;           // rows {tm + 8*i}, i=0..7
    const int tn  = tid >> 3;          // 0..31, cols {tn*7 + j}, j=0..6
    const int bm0 = blockIdx.x * BM;

    // zero the padding concept rows (n = 200..223) once; never rewritten
    for (int q = tid; q < (NP - Ksz) * S2; q += THREADS)
        sp[Ksz * S2 + q] = 0.f;

    float acc[8][7];
    #pragma unroll
    for (int i = 0; i < 8; i++)
        #pragma unroll
        for (int j = 0; j < 7; j++) acc[i][j] = 0.f;

    const int lr = tid & 63;           // x-loader row
    const int lk = (tid >> 6) * 8;     // x-loader k-offset

    for (int k0 = 0; k0 < Csz; k0 += BK) {
        __syncthreads();
        // x tile: [64 rows][32 k]
        {
            const float4* p = reinterpret_cast<const float4*>(
                x + (size_t)(bm0 + lr) * Csz + k0 + lk);
            float4 v0 = p[0], v1 = p[1];
            float* d = sx + lr * S2 + lk;
            d[0] = v0.x; d[1] = v0.y; d[2] = v0.z; d[3] = v0.w;
            d[4] = v1.x; d[5] = v1.y; d[6] = v1.z; d[7] = v1.w;
        }
        // prototype tile: [200 rows][32 k]
        for (int q = tid; q < Ksz * (BK / 4); q += THREADS) {
            int n  = q >> 3;
            int k4 = (q & 7) * 4;
            float4 v = *reinterpret_cast<const float4*>(
                g_proto + (size_t)n * Csz + k0 + k4);
            float* d = sp + n * S2 + k4;
            d[0] = v.x; d[1] = v.y; d[2] = v.z; d[3] = v.w;
        }
        __syncthreads();

        // --- i-group 0 (rows tm+8i, i=0..3), fresh chunk accumulator ---
        {
            float accT[4][7];
            #pragma unroll
            for (int i = 0; i < 4; i++)
                #pragma unroll
                for (int j = 0; j < 7; j++) accT[i][j] = 0.f;
            #pragma unroll
            for (int kk = 0; kk < BK; kk += 2) {
                float2 a2[4], b2[7];
                #pragma unroll
                for (int i = 0; i < 4; i++)
                    a2[i] = *reinterpret_cast<const float2*>(&sx[(tm + 8 * i) * S2 + kk]);
                #pragma unroll
                for (int j = 0; j < 7; j++)
                    b2[j] = *reinterpret_cast<const float2*>(&sp[(tn * 7 + j) * S2 + kk]);
                #pragma unroll
                for (int i = 0; i < 4; i++)
                    #pragma unroll
                    for (int j = 0; j < 7; j++)
                        accT[i][j] = fmaf(a2[i].x, b2[j].x, accT[i][j]);
                #pragma unroll
                for (int i = 0; i < 4; i++)
                    #pragma unroll
                    for (int j = 0; j < 7; j++)
                        accT[i][j] = fmaf(a2[i].y, b2[j].y, accT[i][j]);
            }
            #pragma unroll
            for (int i = 0; i < 4; i++)
                #pragma unroll
                for (int j = 0; j < 7; j++) acc[i][j] += accT[i][j];
        }
        // --- i-group 1 (rows tm+8i, i=4..7) ---
        {
            float accT[4][7];
            #pragma unroll
            for (int i = 0; i < 4; i++)
                #pragma unroll
                for (int j = 0; j < 7; j++) accT[i][j] = 0.f;
            #pragma unroll
            for (int kk = 0; kk < BK; kk += 2) {
                float2 a2[4], b2[7];
                #pragma unroll
                for (int i = 0; i < 4; i++)
                    a2[i] = *reinterpret_cast<const float2*>(&sx[(tm + 8 * (i + 4)) * S2 + kk]);
                #pragma unroll
                for (int j = 0; j < 7; j++)
                    b2[j] = *reinterpret_cast<const float2*>(&sp[(tn * 7 + j) * S2 + kk]);
                #pragma unroll
                for (int i = 0; i < 4; i++)
                    #pragma unroll
                    for (int j = 0; j < 7; j++)
                        accT[i][j] = fmaf(a2[i].x, b2[j].x, accT[i][j]);
                #pragma unroll
                for (int i = 0; i < 4; i++)
                    #pragma unroll
                    for (int j = 0; j < 7; j++)
                        accT[i][j] = fmaf(a2[i].y, b2[j].y, accT[i][j]);
            }
            #pragma unroll
            for (int i = 0; i < 4; i++)
                #pragma unroll
                for (int j = 0; j < 7; j++) acc[i + 4][j] += accT[i][j];
        }
    }
    __syncthreads();

    // ---- epilogue: LayerNorm (two-pass var), top-k threshold, sparse emit ----
    const int lane = tid & 31;
    const int wid  = tid >> 5;
    const int fi   = *dfi;
    const int ktop = Ksz - fi;         // = 20: threshold is the ktop-th largest |v|

    float* feat = smem;                // [32][Ksz], reuses tile smem

    for (int ph = 0; ph < 2; ph++) {
        #pragma unroll
        for (int i = 4 * ph; i < 4 * ph + 4; i++) {
            int rloc = tm + 8 * i - 32 * ph;
            #pragma unroll
            for (int j = 0; j < 7; j++) {
                int n = tn * 7 + j;
                if (n < Ksz) feat[rloc * Ksz + n] = acc[i][j];
            }
        }
        __syncthreads();
        // one warp handles 4 rows
        for (int rr = 0; rr < 4; rr++) {
            int rloc = wid * 4 + rr;
            int row  = bm0 + 32 * ph + rloc;
            float f[7];
            float s1 = 0.f;
            #pragma unroll
            for (int j = 0; j < 7; j++) {
                int n = lane + 32 * j;
                float v = (n < Ksz) ? feat[rloc * Ksz + n] : 0.f;
                f[j] = v;
                s1 += v;
            }
            #pragma unroll
            for (int off = 16; off > 0; off >>= 1)
                s1 += __shfl_xor_sync(0xffffffffu, s1, off);
            float mu = s1 / (float)Ksz;
            float s2 = 0.f;
            #pragma unroll
            for (int j = 0; j < 7; j++) {
                int n = lane + 32 * j;
                if (n < Ksz) {
                    float d = f[j] - mu;
                    s2 = fmaf(d, d, s2);
                }
            }
            #pragma unroll
            for (int off = 16; off > 0; off >>= 1)
                s2 += __shfl_xor_sync(0xffffffffu, s2, off);
            float var  = s2 / (float)Ksz;
            float rstd = 1.f / sqrtf(var + 1e-5f);

            float v[7], av[7], sel[7];
            #pragma unroll
            for (int j = 0; j < 7; j++) {
                int n = lane + 32 * j;
                if (n < Ksz) {
                    float z = (f[j] - mu) * rstd * lnw[n] + lnb[n];
                    v[j] = z; av[j] = fabsf(z); sel[j] = av[j];
                } else { v[j] = 0.f; av[j] = -1.f; sel[j] = -1.f; }
            }
            // extract ktop maxima; last extracted = threshold t
            float t = 0.f;
            for (int it = 0; it < ktop; it++) {
                float lm = sel[0]; int lj = 0;
                #pragma unroll
                for (int j = 1; j < 7; j++) if (sel[j] > lm) { lm = sel[j]; lj = j; }
                float m = lm;
                #pragma unroll
                for (int off = 16; off > 0; off >>= 1)
                    m = fmaxf(m, __shfl_xor_sync(0xffffffffu, m, off));
                unsigned ball = __ballot_sync(0xffffffffu, lm == m);
                int leader = __ffs((int)ball) - 1;
                if (lane == leader) sel[lj] = -2.f;   // remove exactly one instance
                t = m;
            }
            // emit survivors (strictly |v| > t), ascending concept index
            int cnt = 0;
            #pragma unroll
            for (int j = 0; j < 7; j++) {
                bool pred = (av[j] - t > 0.f);
                unsigned msk = __ballot_sync(0xffffffffu, pred);
                if (pred) {
                    int pos = cnt + __popc(msk & ((1u << lane) - 1u));
                    g_sidx[(size_t)row * SLOTS + pos] = lane + 32 * j;
                    g_sval[(size_t)row * SLOTS + pos] = v[j];
                }
                cnt += __popc(msk);
            }
            if (lane == 0) {   // zero-pad so GEMM2 can run a fixed-length loop
                for (int p = cnt; p < ktop; p++) {
                    g_sidx[(size_t)row * SLOTS + p] = 0;
                    g_sval[(size_t)row * SLOTS + p] = 0.f;
                }
            }
        }
        __syncthreads();
    }
}

// ---------------- sparse GEMM2: out = (sum val * fc_wT[idx,:]) + fc_b ----------------
// Restructured for latency hiding: idx/val staged in smem per 32-row batch,
// 8 rows processed concurrently (8 independent LDS->FMA chains per thread).
__global__ __launch_bounds__(TNO, 2)
void k_out_kernel(const float* __restrict__ fcb,
                  const int*   __restrict__ dfi,
                  float* __restrict__ out) {
    extern __shared__ float ws[];              // [Ksz][TNO] = 100KB
    float* sv = ws + Ksz * TNO;                // [32][SLOTS] vals
    int*   si = (int*)(sv + 32 * SLOTS);       // [32][SLOTS] idx

    const int tid = threadIdx.x;
    const int n0  = blockIdx.y * TNO;
    const int col = n0 + tid;
    const bool valid = col < NCsz;

    for (int k = 0; k < Ksz; k++)
        ws[k * TNO + tid] = valid ? g_fcwT[k * NCsz + col] : 0.f;

    const float bb = valid ? fcb[col] : 0.f;
    const int ktop = Ksz - *dfi;               // 20
    const int r0   = blockIdx.x * RB;

    for (int batch = 0; batch < RB; batch += 32) {
        // stage idx/val for 32 rows (coalesced-ish)
        __syncthreads();
        for (int q = tid; q < 32 * ktop; q += TNO) {
            int r = q / ktop, j = q - r * ktop;
            size_t g = (size_t)(r0 + batch + r) * SLOTS + j;
            si[r * SLOTS + j] = g_sidx[g];
            sv[r * SLOTS + j] = g_sval[g];
        }
        __syncthreads();

        for (int rb = 0; rb < 32; rb += 8) {
            float acc[8];
            #pragma unroll
            for (int r = 0; r < 8; r++) acc[r] = 0.f;
            #pragma unroll 4
            for (int j = 0; j < ktop; j++) {
                #pragma unroll
                for (int r = 0; r < 8; r++) {
                    int   idx = si[(rb + r) * SLOTS + j];
                    float v   = sv[(rb + r) * SLOTS + j];
                    acc[r] = fmaf(v, ws[idx * TNO + tid], acc[r]);
                }
            }
            if (valid) {
                #pragma unroll
                for (int r = 0; r < 8; r++)
                    out[(size_t)(r0 + batch + rb + r) * NCsz + col] = acc[r] + bb;
            }
        }
    }
}

// ---------------- launch ----------------
extern "C" void kernel_launch(void* const* d_in, const int* in_sizes, int n_in,
                              void* d_out, int out_size) {
    const float* x        = (const float*)d_in[0];
    const float* concepts = (const float*)d_in[1];
    const float* lnw      = (const float*)d_in[2];
    const float* lnb      = (const float*)d_in[3];
    const float* fcw      = (const float*)d_in[4];
    const float* fcb      = (const float*)d_in[5];
    const int*   dfi      = (const int*)d_in[6];
    float* out = (float*)d_out;

    const int smem2 = Ksz * TNO * (int)sizeof(float)
                    + 32 * SLOTS * (int)(sizeof(float) + sizeof(int));
    cudaFuncSetAttribute(k_out_kernel,
                         cudaFuncAttributeMaxDynamicSharedMemorySize, smem2);

    k_norm_kernel<<<Ksz, THREADS>>>(concepts);
    dim3 trg((NCsz + 31) / 32, (Ksz + 31) / 32);
    k_tr_kernel<<<trg, dim3(32, 8)>>>(fcw);
    k_main_kernel<<<Bsz / BM, THREADS>>>(x, lnw, lnb, dfi);
    dim3 g2(Bsz / RB, (NCsz + TNO - 1) / TNO);
    k_out_kernel<<<g2, TNO, smem2>>>(fcb, dfi, out);
}

// round 5
// speedup vs baseline: 1.1956x; 1.1956x over previous
#include <cuda_runtime.h>
#include <math.h>

// Problem constants (fixed by the dataset instance)
#define Bsz   16384
#define Csz   2048
#define Ksz   200
#define NCsz  1000
#define SLOTS 32

// GEMM1 tiling
#define BM      64
#define BK      32
#define NP      224   // K (concept) dim padded 200 -> 224 = 32*7
#define S2      36    // padded k-stride in smem
#define THREADS 256

// GEMM2 tiling
#define TNO2 256      // output cols per block (128 threads x 2 cols)
#define RB   128      // rows per block

// ---------------- device scratch (no allocations allowed) ----------------
__device__ float g_proto[Ksz * Csz];                    // normalized prototypes
__device__ __align__(16) float g_fcwT[Ksz * NCsz];      // fc_w transposed: [K][NC]
__device__ int   g_sidx[Bsz * SLOTS];                   // per-row surviving indices
__device__ float g_sval[Bsz * SLOTS];                   // per-row surviving LN'd values

// ---------------- normalize prototypes exactly like the reference ----------------
__global__ void k_norm_kernel(const float* __restrict__ concepts) {
    __shared__ float red[THREADS];
    __shared__ float nrm;
    int k = blockIdx.x;
    const float* row = concepts + (size_t)k * Csz;
    float s = 0.f;
    for (int c = threadIdx.x; c < Csz; c += THREADS) {
        float v = row[c];
        s = fmaf(v, v, s);
    }
    red[threadIdx.x] = s;
    __syncthreads();
    for (int off = THREADS / 2; off > 0; off >>= 1) {
        if (threadIdx.x < off) red[threadIdx.x] += red[threadIdx.x + off];
        __syncthreads();
    }
    if (threadIdx.x == 0) nrm = fmaxf(sqrtf(red[0]), 1e-12f);
    __syncthreads();
    float n = nrm;
    for (int c = threadIdx.x; c < Csz; c += THREADS)
        g_proto[(size_t)k * Csz + c] = row[c] / n;   // div.rn, matches F.normalize
}

// ---------------- tiled transpose fc_w [NC,K] -> [K,NC] ----------------
__global__ void k_tr_kernel(const float* __restrict__ fc_w) {
    __shared__ float tile[32][33];
    const int n0 = blockIdx.x * 32;
    const int k0 = blockIdx.y * 32;
    const int tx = threadIdx.x;       // 0..31
    const int ty = threadIdx.y;       // 0..7
    #pragma unroll
    for (int i = 0; i < 32; i += 8) {
        int n = n0 + ty + i, k = k0 + tx;
        tile[ty + i][tx] = (n < NCsz && k < Ksz) ? fc_w[(size_t)n * Ksz + k] : 0.f;
    }
    __syncthreads();
    #pragma unroll
    for (int i = 0; i < 32; i += 8) {
        int k = k0 + ty + i, n = n0 + tx;
        if (k < Ksz && n < NCsz)
            g_fcwT[(size_t)k * NCsz + n] = tile[tx][ty + i];
    }
}

// ---------------- fused GEMM1 + LayerNorm + top-k select ----------------
// EXACT round-3 code (known 610us, known rel_err): scalar smem operand loads,
// chunked accumulation per BK tile, two i-groups of 4 rows.
__global__ __launch_bounds__(THREADS, 2)
void k_main_kernel(const float* __restrict__ x,
                   const float* __restrict__ lnw,
                   const float* __restrict__ lnb,
                   const int*   __restrict__ dfi) {
    __shared__ float smem[(BM + NP) * S2];   // 10368 floats (reused as feat[32][200])
    float* sx = smem;                  // [BM][S2]
    float* sp = smem + BM * S2;        // [NP][S2]

    const int tid = threadIdx.x;
    const int tm  = tid & 7;           // rows {tm + 8*i}, i=0..7
    const int tn  = tid >> 3;          // 0..31, cols {tn*7 + j}, j=0..6
    const int bm0 = blockIdx.x * BM;

    for (int q = tid; q < (NP - Ksz) * S2; q += THREADS)
        sp[Ksz * S2 + q] = 0.f;

    float acc[8][7];
    #pragma unroll
    for (int i = 0; i < 8; i++)
        #pragma unroll
        for (int j = 0; j < 7; j++) acc[i][j] = 0.f;

    const int lr = tid & 63;           // x-loader row
    const int lk = (tid >> 6) * 8;     // x-loader k-offset

    for (int k0 = 0; k0 < Csz; k0 += BK) {
        __syncthreads();
        {
            const float4* p = reinterpret_cast<const float4*>(
                x + (size_t)(bm0 + lr) * Csz + k0 + lk);
            float4 v0 = p[0], v1 = p[1];
            float* d = sx + lr * S2 + lk;
            d[0] = v0.x; d[1] = v0.y; d[2] = v0.z; d[3] = v0.w;
            d[4] = v1.x; d[5] = v1.y; d[6] = v1.z; d[7] = v1.w;
        }
        for (int q = tid; q < Ksz * (BK / 4); q += THREADS) {
            int n  = q >> 3;
            int k4 = (q & 7) * 4;
            float4 v = *reinterpret_cast<const float4*>(
                g_proto + (size_t)n * Csz + k0 + k4);
            float* d = sp + n * S2 + k4;
            d[0] = v.x; d[1] = v.y; d[2] = v.z; d[3] = v.w;
        }
        __syncthreads();

        {
            float accT[4][7];
            #pragma unroll
            for (int i = 0; i < 4; i++)
                #pragma unroll
                for (int j = 0; j < 7; j++) accT[i][j] = 0.f;
            #pragma unroll 8
            for (int kk = 0; kk < BK; kk++) {
                float a[4], b[7];
                #pragma unroll
                for (int i = 0; i < 4; i++) a[i] = sx[(tm + 8 * i) * S2 + kk];
                #pragma unroll
                for (int j = 0; j < 7; j++) b[j] = sp[(tn * 7 + j) * S2 + kk];
                #pragma unroll
                for (int i = 0; i < 4; i++)
                    #pragma unroll
                    for (int j = 0; j < 7; j++)
                        accT[i][j] = fmaf(a[i], b[j], accT[i][j]);
            }
            #pragma unroll
            for (int i = 0; i < 4; i++)
                #pragma unroll
                for (int j = 0; j < 7; j++) acc[i][j] += accT[i][j];
        }
        {
            float accT[4][7];
            #pragma unroll
            for (int i = 0; i < 4; i++)
                #pragma unroll
                for (int j = 0; j < 7; j++) accT[i][j] = 0.f;
            #pragma unroll 8
            for (int kk = 0; kk < BK; kk++) {
                float a[4], b[7];
                #pragma unroll
                for (int i = 0; i < 4; i++) a[i] = sx[(tm + 8 * (i + 4)) * S2 + kk];
                #pragma unroll
                for (int j = 0; j < 7; j++) b[j] = sp[(tn * 7 + j) * S2 + kk];
                #pragma unroll
                for (int i = 0; i < 4; i++)
                    #pragma unroll
                    for (int j = 0; j < 7; j++)
                        accT[i][j] = fmaf(a[i], b[j], accT[i][j]);
            }
            #pragma unroll
            for (int i = 0; i < 4; i++)
                #pragma unroll
                for (int j = 0; j < 7; j++) acc[i + 4][j] += accT[i][j];
        }
    }
    __syncthreads();

    // ---- epilogue: LayerNorm (two-pass var), top-k threshold, sparse emit ----
    const int lane = tid & 31;
    const int wid  = tid >> 5;
    const int fi   = *dfi;
    const int ktop = Ksz - fi;         // = 20

    float* feat = smem;                // [32][Ksz]

    for (int ph = 0; ph < 2; ph++) {
        #pragma unroll
        for (int i = 4 * ph; i < 4 * ph + 4; i++) {
            int rloc = tm + 8 * i - 32 * ph;
            #pragma unroll
            for (int j = 0; j < 7; j++) {
                int n = tn * 7 + j;
                if (n < Ksz) feat[rloc * Ksz + n] = acc[i][j];
            }
        }
        __syncthreads();
        for (int rr = 0; rr < 4; rr++) {
            int rloc = wid * 4 + rr;
            int row  = bm0 + 32 * ph + rloc;
            float f[7];
            float s1 = 0.f;
            #pragma unroll
            for (int j = 0; j < 7; j++) {
                int n = lane + 32 * j;
                float v = (n < Ksz) ? feat[rloc * Ksz + n] : 0.f;
                f[j] = v;
                s1 += v;
            }
            #pragma unroll
            for (int off = 16; off > 0; off >>= 1)
                s1 += __shfl_xor_sync(0xffffffffu, s1, off);
            float mu = s1 / (float)Ksz;
            float s2 = 0.f;
            #pragma unroll
            for (int j = 0; j < 7; j++) {
                int n = lane + 32 * j;
                if (n < Ksz) {
                    float d = f[j] - mu;
                    s2 = fmaf(d, d, s2);
                }
            }
            #pragma unroll
            for (int off = 16; off > 0; off >>= 1)
                s2 += __shfl_xor_sync(0xffffffffu, s2, off);
            float var  = s2 / (float)Ksz;
            float rstd = 1.f / sqrtf(var + 1e-5f);

            float v[7], av[7], sel[7];
            #pragma unroll
            for (int j = 0; j < 7; j++) {
                int n = lane + 32 * j;
                if (n < Ksz) {
                    float z = (f[j] - mu) * rstd * lnw[n] + lnb[n];
                    v[j] = z; av[j] = fabsf(z); sel[j] = av[j];
                } else { v[j] = 0.f; av[j] = -1.f; sel[j] = -1.f; }
            }
            float t = 0.f;
            for (int it = 0; it < ktop; it++) {
                float lm = sel[0]; int lj = 0;
                #pragma unroll
                for (int j = 1; j < 7; j++) if (sel[j] > lm) { lm = sel[j]; lj = j; }
                float m = lm;
                #pragma unroll
                for (int off = 16; off > 0; off >>= 1)
                    m = fmaxf(m, __shfl_xor_sync(0xffffffffu, m, off));
                unsigned ball = __ballot_sync(0xffffffffu, lm == m);
                int leader = __ffs((int)ball) - 1;
                if (lane == leader) sel[lj] = -2.f;
                t = m;
            }
            int cnt = 0;
            #pragma unroll
            for (int j = 0; j < 7; j++) {
                bool pred = (av[j] - t > 0.f);
                unsigned msk = __ballot_sync(0xffffffffu, pred);
                if (pred) {
                    int pos = cnt + __popc(msk & ((1u << lane) - 1u));
                    g_sidx[(size_t)row * SLOTS + pos] = lane + 32 * j;
                    g_sval[(size_t)row * SLOTS + pos] = v[j];
                }
                cnt += __popc(msk);
            }
            if (lane == 0) {
                for (int p = cnt; p < ktop; p++) {
                    g_sidx[(size_t)row * SLOTS + p] = 0;
                    g_sval[(size_t)row * SLOTS + p] = 0.f;
                }
            }
        }
        __syncthreads();
    }
}

// ---------------- sparse GEMM2 v3 ----------------
// Crossbar-wavefront minimized: (val,idx) packed into one 8-byte broadcast,
// each thread owns 2 adjacent output cols (ws as float2, 256 cols/block).
// Per-output FMA chain identical to round 3/4 (ascending j, bias last).
__global__ __launch_bounds__(128, 1)
void k_out_kernel(const float* __restrict__ fcb,
                  const int*   __restrict__ dfi,
                  float* __restrict__ out) {
    extern __shared__ float2 ws2[];                 // [Ksz][128] float2 = 200KB
    float2* pk = ws2 + Ksz * 128;                   // [32][SLOTS] (val, idx-bits)

    const int tid  = threadIdx.x;                   // 0..127
    const int n0   = blockIdx.y * TNO2;
    const int col0 = n0 + 2 * tid;
    const bool v0  = col0 < NCsz;
    const bool v1  = col0 + 1 < NCsz;

    // stage fc_wT columns [n0, n0+256) as float2 rows
    for (int k = 0; k < Ksz; k++) {
        float2 w;
        if (v1)      w = *reinterpret_cast<const float2*>(&g_fcwT[(size_t)k * NCsz + col0]);
        else if (v0) w = make_float2(g_fcwT[(size_t)k * NCsz + col0], 0.f);
        else         w = make_float2(0.f, 0.f);
        ws2[k * 128 + tid] = w;
    }

    float2 bb;
    bb.x = v0 ? fcb[col0] : 0.f;
    bb.y = v1 ? fcb[col0 + 1] : 0.f;
    const int ktop = Ksz - *dfi;                    // 20
    const int r0   = blockIdx.x * RB;

    for (int batch = 0; batch < RB; batch += 32) {
        __syncthreads();
        // stage packed (val, idx) for 32 rows
        for (int q = tid; q < 32 * ktop; q += 128) {
            int r = q / ktop, j = q - r * ktop;
            size_t g = (size_t)(r0 + batch + r) * SLOTS + j;
            pk[r * SLOTS + j] = make_float2(g_sval[g], __int_as_float(g_sidx[g]));
        }
        __syncthreads();

        for (int rb = 0; rb < 32; rb += 8) {
            float2 acc[8];
            #pragma unroll
            for (int r = 0; r < 8; r++) acc[r] = make_float2(0.f, 0.f);
            #pragma unroll 4
            for (int j = 0; j < ktop; j++) {
                #pragma unroll
                for (int r = 0; r < 8; r++) {
                    float2 p = pk[(rb + r) * SLOTS + j];    // 8B broadcast
                    int idx  = __float_as_int(p.y);
                    float2 w = ws2[idx * 128 + tid];        // 8B per lane
                    acc[r].x = fmaf(p.x, w.x, acc[r].x);
                    acc[r].y = fmaf(p.x, w.y, acc[r].y);
                }
            }
            #pragma unroll
            for (int r = 0; r < 8; r++) {
                size_t row = (size_t)(r0 + batch + rb + r);
                if (v1) {
                    float2 o = make_float2(acc[r].x + bb.x, acc[r].y + bb.y);
                    *reinterpret_cast<float2*>(&out[row * NCsz + col0]) = o;
                } else if (v0) {
                    out[row * NCsz + col0] = acc[r].x + bb.x;
                }
            }
        }
    }
}

// ---------------- launch ----------------
extern "C" void kernel_launch(void* const* d_in, const int* in_sizes, int n_in,
                              void* d_out, int out_size) {
    const float* x        = (const float*)d_in[0];
    const float* concepts = (const float*)d_in[1];
    const float* lnw      = (const float*)d_in[2];
    const float* lnb      = (const float*)d_in[3];
    const float* fcw      = (const float*)d_in[4];
    const float* fcb      = (const float*)d_in[5];
    const int*   dfi      = (const int*)d_in[6];
    float* out = (float*)d_out;

    const int smem2 = Ksz * 128 * (int)sizeof(float2)
                    + 32 * SLOTS * (int)sizeof(float2);
    cudaFuncSetAttribute(k_out_kernel,
                         cudaFuncAttributeMaxDynamicSharedMemorySize, smem2);

    k_norm_kernel<<<Ksz, THREADS>>>(concepts);
    dim3 trg((NCsz + 31) / 32, (Ksz + 31) / 32);
    k_tr_kernel<<<trg, dim3(32, 8)>>>(fcw);
    k_main_kernel<<<Bsz / BM, THREADS>>>(x, lnw, lnb, dfi);
    dim3 g2(Bsz / RB, (NCsz + TNO2 - 1) / TNO2);
    k_out_kernel<<<g2, 128, smem2>>>(fcb, dfi, out);
}

// round 6
// speedup vs baseline: 1.5471x; 1.2940x over previous
#include <cuda_runtime.h>
#include <math.h>

// Problem constants (fixed by the dataset instance)
#define Bsz   16384
#define Csz   2048
#define Ksz   200
#define NCsz  1000
#define SLOTS 32

// GEMM1 tiling
#define BM      64
#define BK      32
#define NP      224   // K (concept) dim padded 200 -> 224 = 32*7
#define S2      36    // padded k-stride in smem
#define THREADS 256

// GEMM2 tiling (v4)
#define TNO 128       // output cols per block (32 lanes x float4)
#define RB  128       // rows per block

// ---------------- device scratch (no allocations allowed) ----------------
__device__ float g_proto[Ksz * Csz];                    // normalized prototypes
__device__ __align__(16) float g_fcwT[Ksz * NCsz];      // fc_w transposed: [K][NC]
__device__ int   g_sidx[Bsz * SLOTS];                   // per-row surviving indices
__device__ float g_sval[Bsz * SLOTS];                   // per-row surviving LN'd values

// ---------------- normalize prototypes exactly like the reference ----------------
__global__ void k_norm_kernel(const float* __restrict__ concepts) {
    __shared__ float red[THREADS];
    __shared__ float nrm;
    int k = blockIdx.x;
    const float* row = concepts + (size_t)k * Csz;
    float s = 0.f;
    for (int c = threadIdx.x; c < Csz; c += THREADS) {
        float v = row[c];
        s = fmaf(v, v, s);
    }
    red[threadIdx.x] = s;
    __syncthreads();
    for (int off = THREADS / 2; off > 0; off >>= 1) {
        if (threadIdx.x < off) red[threadIdx.x] += red[threadIdx.x + off];
        __syncthreads();
    }
    if (threadIdx.x == 0) nrm = fmaxf(sqrtf(red[0]), 1e-12f);
    __syncthreads();
    float n = nrm;
    for (int c = threadIdx.x; c < Csz; c += THREADS)
        g_proto[(size_t)k * Csz + c] = row[c] / n;   // div.rn, matches F.normalize
}

// ---------------- tiled transpose fc_w [NC,K] -> [K,NC] ----------------
__global__ void k_tr_kernel(const float* __restrict__ fc_w) {
    __shared__ float tile[32][33];
    const int n0 = blockIdx.x * 32;
    const int k0 = blockIdx.y * 32;
    const int tx = threadIdx.x;       // 0..31
    const int ty = threadIdx.y;       // 0..7
    #pragma unroll
    for (int i = 0; i < 32; i += 8) {
        int n = n0 + ty + i, k = k0 + tx;
        tile[ty + i][tx] = (n < NCsz && k < Ksz) ? fc_w[(size_t)n * Ksz + k] : 0.f;
    }
    __syncthreads();
    #pragma unroll
    for (int i = 0; i < 32; i += 8) {
        int k = k0 + ty + i, n = n0 + tx;
        if (k < Ksz && n < NCsz)
            g_fcwT[(size_t)k * NCsz + n] = tile[tx][ty + i];
    }
}

// ---------------- fused GEMM1 + LayerNorm + top-k select ----------------
// EXACT round-3 code (known 610us, known rel_err).
__global__ __launch_bounds__(THREADS, 2)
void k_main_kernel(const float* __restrict__ x,
                   const float* __restrict__ lnw,
                   const float* __restrict__ lnb,
                   const int*   __restrict__ dfi) {
    __shared__ float smem[(BM + NP) * S2];   // 10368 floats (reused as feat[32][200])
    float* sx = smem;                  // [BM][S2]
    float* sp = smem + BM * S2;        // [NP][S2]

    const int tid = threadIdx.x;
    const int tm  = tid & 7;           // rows {tm + 8*i}, i=0..7
    const int tn  = tid >> 3;          // 0..31, cols {tn*7 + j}, j=0..6
    const int bm0 = blockIdx.x * BM;

    for (int q = tid; q < (NP - Ksz) * S2; q += THREADS)
        sp[Ksz * S2 + q] = 0.f;

    float acc[8][7];
    #pragma unroll
    for (int i = 0; i < 8; i++)
        #pragma unroll
        for (int j = 0; j < 7; j++) acc[i][j] = 0.f;

    const int lr = tid & 63;           // x-loader row
    const int lk = (tid >> 6) * 8;     // x-loader k-offset

    for (int k0 = 0; k0 < Csz; k0 += BK) {
        __syncthreads();
        {
            const float4* p = reinterpret_cast<const float4*>(
                x + (size_t)(bm0 + lr) * Csz + k0 + lk);
            float4 v0 = p[0], v1 = p[1];
            float* d = sx + lr * S2 + lk;
            d[0] = v0.x; d[1] = v0.y; d[2] = v0.z; d[3] = v0.w;
            d[4] = v1.x; d[5] = v1.y; d[6] = v1.z; d[7] = v1.w;
        }
        for (int q = tid; q < Ksz * (BK / 4); q += THREADS) {
            int n  = q >> 3;
            int k4 = (q & 7) * 4;
            float4 v = *reinterpret_cast<const float4*>(
                g_proto + (size_t)n * Csz + k0 + k4);
            float* d = sp + n * S2 + k4;
            d[0] = v.x; d[1] = v.y; d[2] = v.z; d[3] = v.w;
        }
        __syncthreads();

        {
            float accT[4][7];
            #pragma unroll
            for (int i = 0; i < 4; i++)
                #pragma unroll
                for (int j = 0; j < 7; j++) accT[i][j] = 0.f;
            #pragma unroll 8
            for (int kk = 0; kk < BK; kk++) {
                float a[4], b[7];
                #pragma unroll
                for (int i = 0; i < 4; i++) a[i] = sx[(tm + 8 * i) * S2 + kk];
                #pragma unroll
                for (int j = 0; j < 7; j++) b[j] = sp[(tn * 7 + j) * S2 + kk];
                #pragma unroll
                for (int i = 0; i < 4; i++)
                    #pragma unroll
                    for (int j = 0; j < 7; j++)
                        accT[i][j] = fmaf(a[i], b[j], accT[i][j]);
            }
            #pragma unroll
            for (int i = 0; i < 4; i++)
                #pragma unroll
                for (int j = 0; j < 7; j++) acc[i][j] += accT[i][j];
        }
        {
            float accT[4][7];
            #pragma unroll
            for (int i = 0; i < 4; i++)
                #pragma unroll
                for (int j = 0; j < 7; j++) accT[i][j] = 0.f;
            #pragma unroll 8
            for (int kk = 0; kk < BK; kk++) {
                float a[4], b[7];
                #pragma unroll
                for (int i = 0; i < 4; i++) a[i] = sx[(tm + 8 * (i + 4)) * S2 + kk];
                #pragma unroll
                for (int j = 0; j < 7; j++) b[j] = sp[(tn * 7 + j) * S2 + kk];
                #pragma unroll
                for (int i = 0; i < 4; i++)
                    #pragma unroll
                    for (int j = 0; j < 7; j++)
                        accT[i][j] = fmaf(a[i], b[j], accT[i][j]);
            }
            #pragma unroll
            for (int i = 0; i < 4; i++)
                #pragma unroll
                for (int j = 0; j < 7; j++) acc[i + 4][j] += accT[i][j];
        }
    }
    __syncthreads();

    // ---- epilogue: LayerNorm (two-pass var), top-k threshold, sparse emit ----
    const int lane = tid & 31;
    const int wid  = tid >> 5;
    const int fi   = *dfi;
    const int ktop = Ksz - fi;         // = 20

    float* feat = smem;                // [32][Ksz]

    for (int ph = 0; ph < 2; ph++) {
        #pragma unroll
        for (int i = 4 * ph; i < 4 * ph + 4; i++) {
            int rloc = tm + 8 * i - 32 * ph;
            #pragma unroll
            for (int j = 0; j < 7; j++) {
                int n = tn * 7 + j;
                if (n < Ksz) feat[rloc * Ksz + n] = acc[i][j];
            }
        }
        __syncthreads();
        for (int rr = 0; rr < 4; rr++) {
            int rloc = wid * 4 + rr;
            int row  = bm0 + 32 * ph + rloc;
            float f[7];
            float s1 = 0.f;
            #pragma unroll
            for (int j = 0; j < 7; j++) {
                int n = lane + 32 * j;
                float v = (n < Ksz) ? feat[rloc * Ksz + n] : 0.f;
                f[j] = v;
                s1 += v;
            }
            #pragma unroll
            for (int off = 16; off > 0; off >>= 1)
                s1 += __shfl_xor_sync(0xffffffffu, s1, off);
            float mu = s1 / (float)Ksz;
            float s2 = 0.f;
            #pragma unroll
            for (int j = 0; j < 7; j++) {
                int n = lane + 32 * j;
                if (n < Ksz) {
                    float d = f[j] - mu;
                    s2 = fmaf(d, d, s2);
                }
            }
            #pragma unroll
            for (int off = 16; off > 0; off >>= 1)
                s2 += __shfl_xor_sync(0xffffffffu, s2, off);
            float var  = s2 / (float)Ksz;
            float rstd = 1.f / sqrtf(var + 1e-5f);

            float v[7], av[7], sel[7];
            #pragma unroll
            for (int j = 0; j < 7; j++) {
                int n = lane + 32 * j;
                if (n < Ksz) {
                    float z = (f[j] - mu) * rstd * lnw[n] + lnb[n];
                    v[j] = z; av[j] = fabsf(z); sel[j] = av[j];
                } else { v[j] = 0.f; av[j] = -1.f; sel[j] = -1.f; }
            }
            float t = 0.f;
            for (int it = 0; it < ktop; it++) {
                float lm = sel[0]; int lj = 0;
                #pragma unroll
                for (int j = 1; j < 7; j++) if (sel[j] > lm) { lm = sel[j]; lj = j; }
                float m = lm;
                #pragma unroll
                for (int off = 16; off > 0; off >>= 1)
                    m = fmaxf(m, __shfl_xor_sync(0xffffffffu, m, off));
                unsigned ball = __ballot_sync(0xffffffffu, lm == m);
                int leader = __ffs((int)ball) - 1;
                if (lane == leader) sel[lj] = -2.f;
                t = m;
            }
            int cnt = 0;
            #pragma unroll
            for (int j = 0; j < 7; j++) {
                bool pred = (av[j] - t > 0.f);
                unsigned msk = __ballot_sync(0xffffffffu, pred);
                if (pred) {
                    int pos = cnt + __popc(msk & ((1u << lane) - 1u));
                    g_sidx[(size_t)row * SLOTS + pos] = lane + 32 * j;
                    g_sval[(size_t)row * SLOTS + pos] = v[j];
                }
                cnt += __popc(msk);
            }
            if (lane == 0) {
                for (int p = cnt; p < ktop; p++) {
                    g_sidx[(size_t)row * SLOTS + p] = 0;
                    g_sval[(size_t)row * SLOTS + p] = 0.f;
                }
            }
        }
        __syncthreads();
    }
}

// ---------------- sparse GEMM2 v4 ----------------
// 256 threads = 8 warps; warp w owns 4 rows of each 32-row batch; each lane
// owns 4 adjacent cols (LDS.128 ws reads). Packed (val,idx) 8B broadcast.
// Per-output FMA chain identical to rounds 3-5 (ascending j, bias last).
__global__ __launch_bounds__(256, 2)
void k_out_kernel(const float* __restrict__ fcb,
                  const int*   __restrict__ dfi,
                  float* __restrict__ out) {
    extern __shared__ float4 ws4[];                 // [Ksz][32] float4 = 100KB
    float2* pk = (float2*)(ws4 + Ksz * 32);         // [32][SLOTS] packed (val, idx)

    const int tid  = threadIdx.x;                   // 0..255
    const int lane = tid & 31;
    const int wid  = tid >> 5;                      // 0..7: row group
    const int cb   = blockIdx.y;
    const int col0 = cb * TNO + lane * 4;
    const bool vall = (col0 + 3) < NCsz;            // full float4 valid (always all-or-nothing here)

    // stage fc_wT tile [200][128 cols] as float4
    for (int q = tid; q < Ksz * 32; q += 256) {
        int k = q >> 5, t4 = q & 31;
        int c = cb * TNO + t4 * 4;
        float4 w;
        if (c + 3 < NCsz) {
            w = *reinterpret_cast<const float4*>(&g_fcwT[(size_t)k * NCsz + c]);
        } else {
            w.x = (c + 0 < NCsz) ? g_fcwT[(size_t)k * NCsz + c + 0] : 0.f;
            w.y = (c + 1 < NCsz) ? g_fcwT[(size_t)k * NCsz + c + 1] : 0.f;
            w.z = (c + 2 < NCsz) ? g_fcwT[(size_t)k * NCsz + c + 2] : 0.f;
            w.w = 0.f;
        }
        ws4[q] = w;
    }

    float4 bb;
    bb.x = (col0 + 0 < NCsz) ? fcb[col0 + 0] : 0.f;
    bb.y = (col0 + 1 < NCsz) ? fcb[col0 + 1] : 0.f;
    bb.z = (col0 + 2 < NCsz) ? fcb[col0 + 2] : 0.f;
    bb.w = (col0 + 3 < NCsz) ? fcb[col0 + 3] : 0.f;
    const int ktop = Ksz - *dfi;                    // 20
    const int r0   = blockIdx.x * RB;

    for (int batch = 0; batch < RB; batch += 32) {
        __syncthreads();
        // stage packed (val, idx) for 32 rows
        for (int q = tid; q < 32 * ktop; q += 256) {
            int r = q / ktop, j = q - r * ktop;
            size_t g = (size_t)(r0 + batch + r) * SLOTS + j;
            pk[r * SLOTS + j] = make_float2(g_sval[g], __int_as_float(g_sidx[g]));
        }
        __syncthreads();

        // warp wid processes rows {wid*4 + r}, r=0..3
        float4 acc[4];
        #pragma unroll
        for (int r = 0; r < 4; r++) acc[r] = make_float4(0.f, 0.f, 0.f, 0.f);
        const float2* pkr = pk + (wid * 4) * SLOTS;
        #pragma unroll 5
        for (int j = 0; j < ktop; j++) {
            #pragma unroll
            for (int r = 0; r < 4; r++) {
                float2 p = pkr[r * SLOTS + j];          // 8B broadcast
                int idx  = __float_as_int(p.y);
                float4 w = ws4[idx * 32 + lane];        // LDS.128
                acc[r].x = fmaf(p.x, w.x, acc[r].x);
                acc[r].y = fmaf(p.x, w.y, acc[r].y);
                acc[r].z = fmaf(p.x, w.z, acc[r].z);
                acc[r].w = fmaf(p.x, w.w, acc[r].w);
            }
        }
        #pragma unroll
        for (int r = 0; r < 4; r++) {
            size_t row = (size_t)(r0 + batch + wid * 4 + r);
            if (vall) {
                float4 o = make_float4(acc[r].x + bb.x, acc[r].y + bb.y,
                                       acc[r].z + bb.z, acc[r].w + bb.w);
                *reinterpret_cast<float4*>(&out[row * NCsz + col0]) = o;
            } else {
                if (col0 + 0 < NCsz) out[row * NCsz + col0 + 0] = acc[r].x + bb.x;
                if (col0 + 1 < NCsz) out[row * NCsz + col0 + 1] = acc[r].y + bb.y;
                if (col0 + 2 < NCsz) out[row * NCsz + col0 + 2] = acc[r].z + bb.z;
            }
        }
    }
}

// ---------------- launch ----------------
extern "C" void kernel_launch(void* const* d_in, const int* in_sizes, int n_in,
                              void* d_out, int out_size) {
    const float* x        = (const float*)d_in[0];
    const float* concepts = (const float*)d_in[1];
    const float* lnw      = (const float*)d_in[2];
    const float* lnb      = (const float*)d_in[3];
    const float* fcw      = (const float*)d_in[4];
    const float* fcb      = (const float*)d_in[5];
    const int*   dfi      = (const int*)d_in[6];
    float* out = (float*)d_out;

    const int smem2 = Ksz * 32 * (int)sizeof(float4)
                    + 32 * SLOTS * (int)sizeof(float2);   // 100KB + 8KB
    cudaFuncSetAttribute(k_out_kernel,
                         cudaFuncAttributeMaxDynamicSharedMemorySize, smem2);

    k_norm_kernel<<<Ksz, THREADS>>>(concepts);
    dim3 trg((NCsz + 31) / 32, (Ksz + 31) / 32);
    k_tr_kernel<<<trg, dim3(32, 8)>>>(fcw);
    k_main_kernel<<<Bsz / BM, THREADS>>>(x, lnw, lnb, dfi);
    dim3 g2(Bsz / RB, (NCsz + TNO - 1) / TNO);
    k_out_kernel<<<g2, 256, smem2>>>(fcb, dfi, out);
}